// round 9
// baseline (speedup 1.0000x reference)
#include <cuda_runtime.h>
#include <math.h>

// Shape (fixed by the dataset)
#define NB 8
#define NT 4096
#define NH 8
#define ND 64
#define DQ 16                 // float4 lanes over D
#define L 8                   // timesteps per thread
#define NST 4                 // sub-chunks per tile
#define TILE_T (L * NST)      // 32 timesteps per tile
#define NTILES (NT / TILE_T)  // 128 tiles per b
#define F4T (NH * ND / 4)     // float4 stride between consecutive t = 128
#define FULLM 0xFFFFFFFFu

// Decoupled-lookback state: S/Y per (tile, b, h, dq); one flag per (tile, b)
__device__ float4 g_S[NTILES * NB * NH * DQ];
__device__ float4 g_Y[NTILES * NB * NH * DQ];
__device__ int    g_flag[NTILES * NB];        // 0 = empty, 1 = A, 2 = P

static __device__ __forceinline__ void st_release(int* p, int v) {
    asm volatile("st.release.gpu.s32 [%0], %1;" :: "l"(p), "r"(v) : "memory");
}
static __device__ __forceinline__ int ld_acquire(const int* p) {
    int v;
    asm volatile("ld.acquire.gpu.s32 %0, [%1];" : "=r"(v) : "l"(p) : "memory");
    return v;
}
static __device__ __forceinline__ float4 fma4(float s, float4 A, float4 B) {
    return make_float4(fmaf(s, A.x, B.x), fmaf(s, A.y, B.y),
                       fmaf(s, A.z, B.z), fmaf(s, A.w, B.w));
}

__global__ void k_zero() { g_flag[threadIdx.x] = 0; }   // 1024 = NTILES*NB threads

__global__ __launch_bounds__(512, 2) void k_scan(
    const float4* __restrict__ v, const float4* __restrict__ x,
    const float4* __restrict__ v0, const float* __restrict__ sw,
    float4* __restrict__ out)
{
    __shared__ float4 smS[NST * NH * DQ];   // sub-chunk aggregates [st][h][dq], 8 KB
    __shared__ float4 smC[NH * DQ];         // tile-entry carries   [h][dq],     2 KB
    __shared__ int    smWin[2];             // lookback window {count, done}

    const int tid  = threadIdx.x;
    const int st   = tid >> 7;             // 0..3 : sub-chunk (time)
    const int h    = (tid >> 4) & 7;       // 0..7 : head
    const int dq   = tid & 15;             // 0..15: float4 lane over D
    const int tile = blockIdx.x;
    const int b    = blockIdx.y;

    const float a  = 1.0f / (1.0f + expf(-sw[h]));
    const float om = 1.0f - a;
    const float cf = a * (om / fmaxf(om, 1e-6f));
    float a8 = a;
    #pragma unroll
    for (int i = 0; i < 3; ++i) a8 *= a8;          // a^8 = a^L
    const float aT = (a8 * a8) * (a8 * a8);        // a^32 = a^TILE_T

    // Block covers a CONTIGUOUS 64 KB region per array: [tile*32, tile*32+32) x all h x all d
    const int base = ((b * NT + tile * TILE_T + st * L) * NH + h) * (ND / 4) + dq;

    // ---- phase A: local scan of L steps (zero-seeded), y kept in registers ----
    float4 y[L];
    float4 yy = make_float4(0.f, 0.f, 0.f, 0.f);
    #pragma unroll
    for (int i = 0; i < L; ++i) {
        float4 vv = v[base + i * F4T];
        float4 xx = x[base + i * F4T];
        yy.x = fmaf(a, yy.x, fmaf(om, vv.x, cf * xx.x));
        yy.y = fmaf(a, yy.y, fmaf(om, vv.y, cf * xx.y));
        yy.z = fmaf(a, yy.z, fmaf(om, vv.z, cf * xx.z));
        yy.w = fmaf(a, yy.w, fmaf(om, vv.w, cf * xx.w));
        y[i] = yy;
    }
    smS[st * (NH * DQ) + h * DQ + dq] = yy;
    __syncthreads();

    // ---- phase B: exclusive prefix E(st) and tile aggregate (st==3 threads) ----
    // E(st) = sum_{k<st} a8^(st-1-k) S_k  (entry state of sub-chunk st, zero seed)
    float4 E = make_float4(0.f, 0.f, 0.f, 0.f);
    {
        float wgt = 1.0f;
        for (int k = st - 1; k >= 0; --k) {          // st uniform per warp: no divergence
            E = fma4(wgt, smS[k * (NH * DQ) + h * DQ + dq], E);
            wgt *= a8;
        }
    }
    float4 Ablk = make_float4(0.f, 0.f, 0.f, 0.f);
    const int sidx = ((tile * NB + b) * NH + h) * DQ + dq;
    const int fidx = tile * NB + b;
    if (st == 3) {
        float wgt = 1.0f;
        #pragma unroll
        for (int k = 3; k >= 0; --k) {
            Ablk = fma4(wgt, smS[k * (NH * DQ) + h * DQ + dq], Ablk);
            wgt *= a8;
        }
        if (tile > 0) {
            __stcg(&g_S[sidx], Ablk);
            __threadfence();
        }
    }
    __syncthreads();
    if (tid == 0 && tile > 0) st_release(&g_flag[fidx], 1);

    // ---- phase C: windowed parallel lookback ----
    float4 carry;
    if (tile == 0) {
        carry = __ldg(&v0[h * DQ + dq]);
    } else {
        float4 acc  = make_float4(0.f, 0.f, 0.f, 0.f);
        float  wrun = 1.0f;                          // aT^j, running (st==0 threads)
        for (int w = 0;; ++w) {
            if (tid < 32) {                          // warp 0 resolves this window
                const int pred = tile - 1 - (w * 32 + tid);
                for (;;) {
                    int fl = (pred >= 0) ? ld_acquire(&g_flag[pred * NB + b]) : 0;
                    unsigned bp = __ballot_sync(FULLM, fl == 2);
                    unsigned ba = __ballot_sync(FULLM, fl != 0);
                    if (bp) {
                        int js = __ffs(bp) - 1;
                        if (((~ba) & ((1u << js) - 1u)) == 0) {
                            if (tid == 0) { smWin[0] = js; smWin[1] = 1; }
                            break;
                        }
                    } else if (ba == FULLM) {        // full window of aggregates
                        if (tid == 0) { smWin[0] = 32; smWin[1] = 0; }
                        break;
                    }
                    __nanosleep(40);
                }
            }
            __syncthreads();
            const int cnt  = smWin[0];
            const int done = smWin[1];
            if (st == 0) {                           // 128 accumulators, one per (h,dq)
                for (int j = 0; j < cnt; ++j) {
                    const int pred = tile - 1 - (w * 32 + j);
                    acc = fma4(wrun, __ldcg(&g_S[((pred * NB + b) * NH + h) * DQ + dq]), acc);
                    wrun *= aT;
                }
                if (done) {
                    const int pred = tile - 1 - (w * 32 + cnt);
                    acc = fma4(wrun, __ldcg(&g_Y[((pred * NB + b) * NH + h) * DQ + dq]), acc);
                    smC[h * DQ + dq] = acc;
                }
            }
            __syncthreads();
            if (done) break;
        }
        carry = smC[h * DQ + dq];
    }

    // ---- publish inclusive end value P ----
    if (st == 3) {
        __stcg(&g_Y[sidx], fma4(aT, carry, Ablk));
        __threadfence();
    }
    __syncthreads();
    if (tid == 0) st_release(&g_flag[fidx], 2);

    // ---- phase D: apply carry in registers, single contiguous store pass ----
    float p = 1.0f;                                  // a8^st (st <= 3, uniform per warp)
    for (int k = 0; k < st; ++k) p *= a8;
    const float4 c = fma4(p, carry, E);

    float pa = a;
    #pragma unroll
    for (int i = 0; i < L; ++i) {
        out[base + i * F4T] = fma4(pa, c, y[i]);
        pa *= a;
    }
}

extern "C" void kernel_launch(void* const* d_in, const int* in_sizes, int n_in,
                              void* d_out, int out_size)
{
    const float4* v  = (const float4*)d_in[0];   // values   [B,T,H,D] f32
    const float4* x  = (const float4*)d_in[1];   // aux      [B,T,H,D] f32
    const float4* v0 = (const float4*)d_in[2];   // v0       [1,1,H,D] f32
    const float*  sw = (const float*)d_in[3];    // weight   [H,1]     f32

    k_zero<<<1, NTILES * NB>>>();
    k_scan<<<dim3(NTILES, NB), 512>>>(v, x, (const float4*)v0, sw, (float4*)d_out);
}

// round 10
// speedup vs baseline: 1.4499x; 1.4499x over previous
#include <cuda_runtime.h>
#include <math.h>

// Shape (fixed by the dataset)
#define NB 8
#define NT 4096
#define NH 8
#define ND 64
#define DQ 16                 // float4 lanes over D
#define L 8                   // timesteps per thread
#define SUBS 32               // sub-chunks per tile (block = SUBS*DQ = 512 threads)
#define TILE_T (L * SUBS)     // 256 timesteps per tile
#define NTILES (NT / TILE_T)  // 16
#define NBH (NB * NH)         // 64
#define NBLK (NTILES * NBH)   // 1024
#define F4T (NH * ND / 4)     // float4 stride between consecutive t = 128

// Decoupled-lookback state (per tile, per channel). Zero-initialized at load;
// the last block of every launch resets g_flag/g_done back to zero.
__device__ float4 g_S[NTILES * NBH * DQ];   // tile aggregate
__device__ float4 g_Y[NTILES * NBH * DQ];   // tile inclusive end value
__device__ int    g_flag[NTILES * NBH];     // 0 = empty, 1 = A, 2 = P
__device__ int    g_done;                   // finished-block counter

static __device__ __forceinline__ void st_release(int* p, int v) {
    asm volatile("st.release.gpu.s32 [%0], %1;" :: "l"(p), "r"(v) : "memory");
}
static __device__ __forceinline__ int ld_acquire(const int* p) {
    int v;
    asm volatile("ld.acquire.gpu.s32 %0, [%1];" : "=r"(v) : "l"(p) : "memory");
    return v;
}
static __device__ __forceinline__ float4 fma4(float s, float4 A, float4 B) {
    return make_float4(fmaf(s, A.x, B.x), fmaf(s, A.y, B.y),
                       fmaf(s, A.z, B.z), fmaf(s, A.w, B.w));
}

__global__ __launch_bounds__(512, 2) void k_scan(
    const float4* __restrict__ v, const float4* __restrict__ x,
    const float4* __restrict__ v0, const float* __restrict__ sw,
    float4* __restrict__ out)
{
    __shared__ float4 sm[SUBS * DQ];     // aggregates -> exclusive prefixes (in place)
    __shared__ float4 carry_sm[DQ];
    __shared__ int    is_last;

    const int tid  = threadIdx.x;
    const int dq   = tid & 15;
    const int sub  = tid >> 4;
    const int bh   = blockIdx.x;        // channel runs FASTEST in launch order
    const int tile = blockIdx.y;        // tiles launch wave-by-wave, in order
    const int h    = bh & (NH - 1);
    const int b    = bh >> 3;

    const float a  = 1.0f / (1.0f + expf(-sw[h]));
    const float om = 1.0f - a;
    const float cf = a * (om / fmaxf(om, 1e-6f));
    float a8_1 = a;
    #pragma unroll
    for (int i = 0; i < 3; ++i) a8_1 *= a8_1;          // a^8
    const float a8_2  = a8_1 * a8_1;                   // a^16
    const float a8_4  = a8_2 * a8_2;                   // a^32
    const float a8_8  = a8_4 * a8_4;                   // a^64
    const float a8_16 = a8_8 * a8_8;                   // a^128
    const float aT    = a8_16 * a8_16;                 // a^256 = a^TILE_T

    const int base = ((b * NT + tile * TILE_T + sub * L) * NH + h) * (ND / 4) + dq;

    // ---- local scan of L steps, zero-seeded, kept in registers ----
    float4 y[L];
    float4 yy = make_float4(0.f, 0.f, 0.f, 0.f);
    #pragma unroll
    for (int i = 0; i < L; ++i) {
        float4 vv = v[base + i * F4T];
        float4 xx = x[base + i * F4T];
        yy.x = fmaf(a, yy.x, fmaf(om, vv.x, cf * xx.x));
        yy.y = fmaf(a, yy.y, fmaf(om, vv.y, cf * xx.y));
        yy.z = fmaf(a, yy.z, fmaf(om, vv.z, cf * xx.z));
        yy.w = fmaf(a, yy.w, fmaf(om, vv.w, cf * xx.w));
        y[i] = yy;
    }
    sm[sub * DQ + dq] = yy;              // sub-chunk aggregate
    __syncthreads();

    // ---- in-block scan across sub-chunks + lookback (first 16 threads) ----
    if (tid < DQ) {
        float4 I = make_float4(0.f, 0.f, 0.f, 0.f);
        #pragma unroll
        for (int k = 0; k < SUBS; ++k) {
            float4 t4 = sm[k * DQ + tid];
            sm[k * DQ + tid] = I;        // exclusive prefix (entry state, zero seed)
            I.x = fmaf(a8_1, I.x, t4.x);
            I.y = fmaf(a8_1, I.y, t4.y);
            I.z = fmaf(a8_1, I.z, t4.z);
            I.w = fmaf(a8_1, I.w, t4.w);
        }
        const float4 blockagg = I;
        const int sidx = (tile * NBH + bh) * DQ + tid;
        const int fidx = tile * NBH + bh;

        if (tile > 0) {                  // publish aggregate ASAP
            __stcg(&g_S[sidx], blockagg);
            __syncwarp(0x0000FFFFu);
            if (tid == 0) st_release(&g_flag[fidx], 1);
        }

        // lookback for the tile-entry carry (usually 1 hop with this launch order)
        float4 carry;
        if (tile == 0) {
            carry = __ldg(&v0[h * DQ + tid]);
        } else {
            float4 acc = make_float4(0.f, 0.f, 0.f, 0.f);
            float  d   = 1.0f;
            int    j   = tile - 1;
            for (;;) {
                int f = 0;
                if (tid == 0) {
                    do { f = ld_acquire(&g_flag[j * NBH + bh]); } while (f == 0);
                }
                f = __shfl_sync(0x0000FFFFu, f, 0);
                const int pidx = (j * NBH + bh) * DQ + tid;
                if (f == 2) {
                    float4 Y = __ldcg(&g_Y[pidx]);
                    carry = fma4(d, Y, acc);
                    break;
                } else {
                    float4 S = __ldcg(&g_S[pidx]);
                    acc = fma4(d, S, acc);
                    d *= aT;
                    --j;
                }
            }
        }

        // publish inclusive end value
        __stcg(&g_Y[sidx], fma4(aT, carry, blockagg));
        __syncwarp(0x0000FFFFu);
        if (tid == 0) st_release(&g_flag[fidx], 2);

        carry_sm[tid] = carry;
    }
    __syncthreads();

    // ---- apply carry in registers and write output (single store pass) ----
    const float4 carry2 = carry_sm[dq];
    const float4 E = sm[sub * DQ + dq];  // within-tile exclusive prefix
    float p = 1.0f;                      // a8^sub from bits (exact products)
    if (sub & 1)  p *= a8_1;
    if (sub & 2)  p *= a8_2;
    if (sub & 4)  p *= a8_4;
    if (sub & 8)  p *= a8_8;
    if (sub & 16) p *= a8_16;
    const float4 c = fma4(p, carry2, E);

    float pa = a;
    #pragma unroll
    for (int i = 0; i < L; ++i) {
        out[base + i * F4T] = fma4(pa, c, y[i]);
        pa *= a;
    }

    // ---- last finished block resets the lookback state for the next launch ----
    __threadfence();
    if (tid == 0) is_last = (atomicAdd(&g_done, 1) == NBLK - 1);
    __syncthreads();
    if (is_last) {
        for (int i = tid; i < NBLK; i += 512) g_flag[i] = 0;
        if (tid == 0) g_done = 0;
    }
}

extern "C" void kernel_launch(void* const* d_in, const int* in_sizes, int n_in,
                              void* d_out, int out_size)
{
    const float4* v  = (const float4*)d_in[0];   // values   [B,T,H,D] f32
    const float4* x  = (const float4*)d_in[1];   // aux      [B,T,H,D] f32
    const float4* v0 = (const float4*)d_in[2];   // v0       [1,1,H,D] f32
    const float*  sw = (const float*)d_in[3];    // weight   [H,1]     f32

    k_scan<<<dim3(NBH, NTILES), SUBS * DQ>>>(v, x, (const float4*)v0, sw, (float4*)d_out);
}

// round 12
// speedup vs baseline: 1.6493x; 1.1375x over previous
#include <cuda_runtime.h>
#include <math.h>

// Shape (fixed by the dataset)
#define NB 8
#define NT 4096
#define NH 8
#define ND 64
#define DQ 16                 // float4 lanes over D
#define L 8                   // timesteps per thread
#define SUBS 32               // sub-chunks per tile (block = SUBS*DQ = 512 threads)
#define TILE_T (L * SUBS)     // 256 timesteps per tile
#define NTILES (NT / TILE_T)  // 16  (<= 32: whole lookback fits in one warp)
#define NBH (NB * NH)         // 64
#define NBLK (NTILES * NBH)   // 1024
#define F4T (NH * ND / 4)     // float4 stride between consecutive t = 128
#define SMP 17                // padded smem stride (float4 units)
#define FULLM 0xFFFFFFFFu

// Aggregate-only lookback state. Epoch-tagged flags: a flag is "ready" only if
// it equals the current launch's epoch, so stale state from any interrupted
// launch is ignored (no clean reset required).
__device__ float4       g_S[NTILES * NBH * DQ];      // tile aggregates
__device__ int          g_flag[NTILES * NBH * DQ];   // == epoch when ready
__device__ unsigned int g_epoch;                     // bumped once per launch

static __device__ __forceinline__ void st_release(int* p, int v) {
    asm volatile("st.release.gpu.s32 [%0], %1;" :: "l"(p), "r"(v) : "memory");
}
static __device__ __forceinline__ int ld_acquire(const int* p) {
    int v;
    asm volatile("ld.acquire.gpu.s32 %0, [%1];" : "=r"(v) : "l"(p) : "memory");
    return v;
}
static __device__ __forceinline__ float4 fma4(float s, float4 A, float4 B) {
    return make_float4(fmaf(s, A.x, B.x), fmaf(s, A.y, B.y),
                       fmaf(s, A.z, B.z), fmaf(s, A.w, B.w));
}

// Tiny prologue: bump the epoch for this launch. Epoch e (>=1) marks "ready".
__global__ void k_epoch() { atomicAdd(&g_epoch, 1u); }

__global__ __launch_bounds__(512, 2) void k_scan(
    const float4* __restrict__ v, const float4* __restrict__ x,
    const float4* __restrict__ v0, const float* __restrict__ sw,
    float4* __restrict__ out)
{
    __shared__ float4 smT[SUBS * SMP];   // aggregates -> exclusive prefixes (padded)
    __shared__ float4 carry_sm[DQ];

    const int tid  = threadIdx.x;
    const int dq   = tid & 15;
    const int sub  = tid >> 4;
    const int wid  = tid >> 5;          // warp id == dq owned in phases B/C
    const int lane = tid & 31;
    const int bh   = blockIdx.x;        // channel fastest -> tile-major waves
    const int tile = blockIdx.y;
    const int h    = bh & (NH - 1);
    const int b    = bh >> 3;

    const int epoch = (int)g_epoch;     // constant for the whole launch

    const float a  = 1.0f / (1.0f + expf(-sw[h]));
    const float om = 1.0f - a;
    const float cf = a * (om / fmaxf(om, 1e-6f));
    float a8_1 = a;
    #pragma unroll
    for (int i = 0; i < 3; ++i) a8_1 *= a8_1;          // a^8
    const float a8_2  = a8_1 * a8_1;                   // a^16
    const float a8_4  = a8_2 * a8_2;                   // a^32
    const float a8_8  = a8_4 * a8_4;                   // a^64
    const float a8_16 = a8_8 * a8_8;                   // a^128
    const float aT    = a8_16 * a8_16;                 // a^256 = a^TILE_T

    const int base = ((b * NT + tile * TILE_T + sub * L) * NH + h) * (ND / 4) + dq;

    // ---- phase A: local scan of L steps (zero-seeded) in registers ----
    float4 y[L];
    float4 yy = make_float4(0.f, 0.f, 0.f, 0.f);
    #pragma unroll
    for (int i = 0; i < L; ++i) {
        float4 vv = v[base + i * F4T];
        float4 xx = x[base + i * F4T];
        yy.x = fmaf(a, yy.x, fmaf(om, vv.x, cf * xx.x));
        yy.y = fmaf(a, yy.y, fmaf(om, vv.y, cf * xx.y));
        yy.z = fmaf(a, yy.z, fmaf(om, vv.z, cf * xx.z));
        yy.w = fmaf(a, yy.w, fmaf(om, vv.w, cf * xx.w));
        y[i] = yy;
    }
    smT[sub * SMP + dq] = yy;
    __syncthreads();

    // ---- phase B: warp wid KS-scans the 32 sub-aggregates of dq == wid ----
    // I_s = sum_{k<=s} a8^(s-k) S_k   (weighted Kogge-Stone, validated R7/R9)
    float4 I = smT[lane * SMP + wid];
    {
        float f = a8_1;
        #pragma unroll
        for (int o = 1; o < 32; o <<= 1) {
            float4 t;
            t.x = __shfl_up_sync(FULLM, I.x, o);
            t.y = __shfl_up_sync(FULLM, I.y, o);
            t.z = __shfl_up_sync(FULLM, I.z, o);
            t.w = __shfl_up_sync(FULLM, I.w, o);
            if (lane >= o) I = fma4(f, t, I);
            f *= f;
        }
    }
    const int sidx = (tile * NBH + bh) * DQ + wid;
    // publish tile aggregate IMMEDIATELY (lane 31 holds the inclusive total)
    if (lane == 31) {
        __stcg(&g_S[sidx], I);
        st_release(&g_flag[sidx], epoch);
    }
    // exclusive prefix: entry state of sub-chunk s (zero tile seed) = I_{s-1}
    float4 E;
    E.x = __shfl_up_sync(FULLM, I.x, 1);
    E.y = __shfl_up_sync(FULLM, I.y, 1);
    E.z = __shfl_up_sync(FULLM, I.z, 1);
    E.w = __shfl_up_sync(FULLM, I.w, 1);
    if (lane == 0) E = make_float4(0.f, 0.f, 0.f, 0.f);
    smT[lane * SMP + wid] = E;

    // ---- phase C: aggregate-only parallel lookback (no P-chain) ----
    // carry_t = sum_{k<t} aT^k S[t-1-k]  +  aT^t v0     (lane k handles hop k)
    float4 val = make_float4(0.f, 0.f, 0.f, 0.f);
    {
        const float aT2 = aT * aT, aT4 = aT2 * aT2, aT8 = aT4 * aT4, aT16 = aT8 * aT8;
        float dj = 1.0f;                 // aT^lane from bits (exact products)
        if (lane & 1)  dj *= aT;
        if (lane & 2)  dj *= aT2;
        if (lane & 4)  dj *= aT4;
        if (lane & 8)  dj *= aT8;
        if (lane & 16) dj *= aT16;
        if (lane < tile) {
            const int pidx = ((tile - 1 - lane) * NBH + bh) * DQ + wid;
            while (ld_acquire(&g_flag[pidx]) != epoch) __nanosleep(40);
            val = fma4(dj, __ldcg(&g_S[pidx]), val);
        } else if (lane == tile) {
            val = fma4(dj, __ldg(&v0[h * DQ + wid]), val);
        }
        __syncwarp(FULLM);
        #pragma unroll
        for (int o = 16; o >= 1; o >>= 1) {
            val.x += __shfl_xor_sync(FULLM, val.x, o);
            val.y += __shfl_xor_sync(FULLM, val.y, o);
            val.z += __shfl_xor_sync(FULLM, val.z, o);
            val.w += __shfl_xor_sync(FULLM, val.w, o);
        }
    }
    if (lane == 0) carry_sm[wid] = val;
    __syncthreads();

    // ---- phase D: apply carry in registers, single store pass ----
    const float4 carry = carry_sm[dq];
    const float4 E2 = smT[sub * SMP + dq];
    float p = 1.0f;                      // a8^sub from bits (exact products)
    if (sub & 1)  p *= a8_1;
    if (sub & 2)  p *= a8_2;
    if (sub & 4)  p *= a8_4;
    if (sub & 8)  p *= a8_8;
    if (sub & 16) p *= a8_16;
    const float4 c = fma4(p, carry, E2);

    float pa = a;
    #pragma unroll
    for (int i = 0; i < L; ++i) {
        out[base + i * F4T] = fma4(pa, c, y[i]);
        pa *= a;
    }
}

extern "C" void kernel_launch(void* const* d_in, const int* in_sizes, int n_in,
                              void* d_out, int out_size)
{
    const float4* v  = (const float4*)d_in[0];   // values   [B,T,H,D] f32
    const float4* x  = (const float4*)d_in[1];   // aux      [B,T,H,D] f32
    const float4* v0 = (const float4*)d_in[2];   // v0       [1,1,H,D] f32
    const float*  sw = (const float*)d_in[3];    // weight   [H,1]     f32

    k_epoch<<<1, 1>>>();
    k_scan<<<dim3(NBH, NTILES), SUBS * DQ>>>(v, x, (const float4*)v0, sw, (float4*)d_out);
}